// round 1
// baseline (speedup 1.0000x reference)
#include <cuda_runtime.h>
#include <cstdint>

// Problem constants
#define B_    4
#define C_    256
#define H_    64
#define W_    64
#define O_    256
#define KK_   9          // 3x3
#define HW_   4096       // 64*64
#define NPIX  16384      // B*HW
#define KTOT  2304       // C*KK
#define OMCH  27
#define OMSZ  (B_*OMCH*HW_)   // 442368
#define NCHUNK 8              // c-chunks for offset conv

// Scratch (device globals; no allocation allowed)
__device__ float g_om[OMSZ];                 // offset conv result (4,27,64,64)
__device__ float g_om_part[NCHUNK * OMSZ];   // per-chunk partials (deterministic, no atomics)
__device__ float g_wT[KTOT * O_];            // weight transposed: [k][o], k = c*9+kk

// ---------------------------------------------------------------------------
// Kernel 1: transpose weight (O,C,3,3) -> wT[k][o]
// ---------------------------------------------------------------------------
__global__ void transpose_w_kernel(const float* __restrict__ weight) {
    int i = blockIdx.x * 256 + threadIdx.x;   // i = k*256 + o, write-coalesced
    int k = i >> 8;
    int o = i & 255;
    g_wT[i] = weight[o * KTOT + k];
}

// ---------------------------------------------------------------------------
// Kernel 2: offset conv partials.
// grid: (32 pixel-tiles of 512, 8 c-chunks of 32). 128 threads, 4 pixels each.
// Each thread keeps 27 accumulators; weights chunk staged in smem (broadcast LDS).
// ---------------------------------------------------------------------------
__global__ __launch_bounds__(128) void offset_conv_kernel(
    const float* __restrict__ x, const float* __restrict__ w_off)
{
    __shared__ float s_w[OMCH * 288];   // [27][32*9] for this c-chunk

    const int t     = threadIdx.x;
    const int c0    = blockIdx.y * 32;
    const int pbase = blockIdx.x * 512;
    const int b     = pbase >> 12;

    for (int i = t; i < OMCH * 288; i += 128) {
        int j = i / 288, col = i - j * 288;
        s_w[i] = w_off[j * KTOT + c0 * 9 + col];
    }
    __syncthreads();

    int pimg[4], hh[4], ww[4];
#pragma unroll
    for (int p = 0; p < 4; p++) {
        int pix = pbase + t + (p << 7);
        pimg[p] = pix & 4095;
        hh[p] = pimg[p] >> 6;
        ww[p] = pimg[p] & 63;
    }

    float acc[OMCH][4];
#pragma unroll
    for (int j = 0; j < OMCH; j++)
#pragma unroll
        for (int p = 0; p < 4; p++) acc[j][p] = 0.f;

    const float* xb = x + (((size_t)b * C_ + c0) << 12);
    for (int cl = 0; cl < 32; cl++) {
        const float* xc = xb + ((size_t)cl << 12);
#pragma unroll
        for (int kh = 0; kh < 3; kh++) {
#pragma unroll
            for (int kw = 0; kw < 3; kw++) {
                float xv[4];
#pragma unroll
                for (int p = 0; p < 4; p++) {
                    int y  = hh[p] + kh - 1;
                    int xx = ww[p] + kw - 1;
                    bool ok = ((unsigned)y < 64u) && ((unsigned)xx < 64u);
                    xv[p] = ok ? __ldg(xc + (y << 6) + xx) : 0.f;
                }
                int wbase = cl * 9 + kh * 3 + kw;
#pragma unroll
                for (int j = 0; j < OMCH; j++) {
                    float wv = s_w[j * 288 + wbase];
#pragma unroll
                    for (int p = 0; p < 4; p++) acc[j][p] = fmaf(wv, xv[p], acc[j][p]);
                }
            }
        }
    }

    float* dst = g_om_part + (size_t)blockIdx.y * OMSZ + (((size_t)b * OMCH) << 12);
#pragma unroll
    for (int j = 0; j < OMCH; j++)
#pragma unroll
        for (int p = 0; p < 4; p++)
            dst[(j << 12) + pimg[p]] = acc[j][p];
}

// ---------------------------------------------------------------------------
// Kernel 3: reduce partials + bias -> g_om
// ---------------------------------------------------------------------------
__global__ void reduce_om_kernel(const float* __restrict__ b_off) {
    int i = blockIdx.x * 256 + threadIdx.x;   // OMSZ = 1728*256 exactly
    float s = b_off[(i >> 12) % OMCH];
#pragma unroll
    for (int k = 0; k < NCHUNK; k++) s += g_om_part[(size_t)k * OMSZ + i];
    g_om[i] = s;
}

// ---------------------------------------------------------------------------
// Kernel 4: fused bilinear-sample + GEMM.
// grid: (128 pixel-tiles of 128, 2 O-tiles of 128). 256 threads, 8x8 per thread.
// Sampling params (clipped gather indices + mask-folded bilinear weights) are
// computed once per block into smem; col tiles are generated on the fly.
// ---------------------------------------------------------------------------
#define BKC 16   // channels per K-chunk (K-chunk = 16 for one fixed kk)

__global__ __launch_bounds__(256) void deform_gemm_kernel(
    const float* __restrict__ x, const float* __restrict__ bias,
    float* __restrict__ out)
{
    __shared__ uint32_t s_idxA[KK_ * 128];   // idx00 | idx01<<16 (clipped, <=4095)
    __shared__ uint32_t s_idxB[KK_ * 128];   // idx10 | idx11<<16
    __shared__ float4   s_wq[KK_ * 128];     // w00,w01,w10,w11 (mask folded)
    __shared__ float    w_s[BKC][128];
    __shared__ float    col_s[BKC][128];

    const int t     = threadIdx.x;
    const int obase = blockIdx.y * 128;
    const int pbase = blockIdx.x * 128;
    const int b     = pbase >> 12;
    const int pib   = pbase & 4095;          // pixel base within image

    // ---- prologue: sampling params for 9 kk x 128 pixels ----
    for (int e = t; e < KK_ * 128; e += 256) {
        int kk = e >> 7;
        int n  = e & 127;
        int pimg = pib + n;
        int h = pimg >> 6, w = pimg & 63;
        const float* omb = g_om + (((size_t)b * OMCH) << 12) + pimg;
        float dy = omb[(size_t)(2 * kk) << 12];
        float dx = omb[(size_t)(2 * kk + 1) << 12];
        float mv = omb[(size_t)(18 + kk) << 12];
        float m  = 1.0f / (1.0f + expf(-mv));
        int kh = kk / 3, kw = kk - 3 * kh;
        float py = (float)(h - 1 + kh) + dy;
        float px = (float)(w - 1 + kw) + dx;
        float y0f = floorf(py), x0f = floorf(px);
        float ly = py - y0f, lx = px - x0f;
        int y0 = (int)y0f, x0 = (int)x0f;
        int y1 = y0 + 1, x1 = x0 + 1;
        float vy0 = ((unsigned)y0 < 64u) ? 1.f : 0.f;
        float vy1 = ((unsigned)y1 < 64u) ? 1.f : 0.f;
        float vx0 = ((unsigned)x0 < 64u) ? 1.f : 0.f;
        float vx1 = ((unsigned)x1 < 64u) ? 1.f : 0.f;
        int y0c = min(max(y0, 0), 63), y1c = min(max(y1, 0), 63);
        int x0c = min(max(x0, 0), 63), x1c = min(max(x1, 0), 63);
        float w00 = (1.f - ly) * (1.f - lx) * m * vy0 * vx0;
        float w01 = (1.f - ly) * lx * m * vy0 * vx1;
        float w10 = ly * (1.f - lx) * m * vy1 * vx0;
        float w11 = ly * lx * m * vy1 * vx1;
        s_idxA[e] = (uint32_t)(y0c * 64 + x0c) | ((uint32_t)(y0c * 64 + x1c) << 16);
        s_idxB[e] = (uint32_t)(y1c * 64 + x0c) | ((uint32_t)(y1c * 64 + x1c) << 16);
        s_wq[e] = make_float4(w00, w01, w10, w11);
    }
    __syncthreads();

    // ---- main loop ----
    float acc[8][8];
#pragma unroll
    for (int i = 0; i < 8; i++)
#pragma unroll
        for (int j = 0; j < 8; j++) acc[i][j] = 0.f;

    const int tm = t >> 4;       // 0..15 -> o = obase + tm + 16*i
    const int tn = t & 15;       // 0..15 -> n = tn + 16*j
    const float* xb = x + ((size_t)b << 20);   // b*C*HW

    for (int kk = 0; kk < KK_; kk++) {
        for (int c0 = 0; c0 < C_; c0 += BKC) {
            // stage weight tile [BKC][128] (coalesced from transposed weight)
#pragma unroll
            for (int j = 0; j < 8; j++) {
                int i  = t + (j << 8);
                int kl = i >> 7;
                int o  = i & 127;
                w_s[kl][o] = g_wT[((size_t)((c0 + kl) * KK_ + kk) << 8) + obase + o];
            }
            // generate col tile [BKC][128] via bilinear gather
#pragma unroll
            for (int j = 0; j < 8; j++) {
                int i  = t + (j << 8);
                int kl = i >> 7;
                int n  = i & 127;
                int e  = (kk << 7) + n;
                uint32_t ia = s_idxA[e];
                uint32_t ib = s_idxB[e];
                float4 wq = s_wq[e];
                const float* xc = xb + ((size_t)(c0 + kl) << 12);
                float v = wq.x * __ldg(xc + (ia & 0xffffu))
                        + wq.y * __ldg(xc + (ia >> 16))
                        + wq.z * __ldg(xc + (ib & 0xffffu))
                        + wq.w * __ldg(xc + (ib >> 16));
                col_s[kl][n] = v;
            }
            __syncthreads();

#pragma unroll
            for (int kb = 0; kb < BKC; kb++) {
                float a[8], bb[8];
#pragma unroll
                for (int i = 0; i < 8; i++) a[i] = w_s[kb][tm + (i << 4)];
#pragma unroll
                for (int j = 0; j < 8; j++) bb[j] = col_s[kb][tn + (j << 4)];
#pragma unroll
                for (int i = 0; i < 8; i++)
#pragma unroll
                    for (int j = 0; j < 8; j++)
                        acc[i][j] = fmaf(a[i], bb[j], acc[i][j]);
            }
            __syncthreads();
        }
    }

    // ---- epilogue: add bias, coalesced store ----
#pragma unroll
    for (int i = 0; i < 8; i++) {
        int o = obase + tm + (i << 4);
        float bv = __ldg(bias + o);
        float* orow = out + (((size_t)(b * O_ + o)) << 12) + pib;
#pragma unroll
        for (int j = 0; j < 8; j++) {
            orow[tn + (j << 4)] = acc[i][j] + bv;
        }
    }
}

// ---------------------------------------------------------------------------
// Launch
// ---------------------------------------------------------------------------
extern "C" void kernel_launch(void* const* d_in, const int* in_sizes, int n_in,
                              void* d_out, int out_size)
{
    const float* x      = (const float*)d_in[0];
    const float* w_off  = (const float*)d_in[1];
    const float* b_off  = (const float*)d_in[2];
    const float* weight = (const float*)d_in[3];
    const float* bias   = (const float*)d_in[4];
    float* out = (float*)d_out;

    // 1) transpose weight -> g_wT  (589824 = 2304 blocks * 256)
    transpose_w_kernel<<<KTOT, 256>>>(weight);

    // 2) offset conv partials: 32 pixel-tiles x 8 c-chunks, 128 threads
    offset_conv_kernel<<<dim3(32, NCHUNK), 128>>>(x, w_off);

    // 3) reduce + bias -> g_om  (442368 = 1728 * 256)
    reduce_om_kernel<<<OMSZ / 256, 256>>>(b_off);

    // 4) fused sample + GEMM: 128 pixel-tiles x 2 O-tiles, 256 threads
    deform_gemm_kernel<<<dim3(NPIX / 128, 2), 256>>>(x, bias, out);
}

// round 3
// speedup vs baseline: 2.4951x; 2.4951x over previous
#include <cuda_runtime.h>
#include <cuda_bf16.h>
#include <cstdint>

// Problem constants
#define B_    4
#define C_    256
#define H_    64
#define W_    64
#define O_    256
#define KK_   9
#define HW_   4096
#define NPIX  16384
#define KTOT  2304
#define OMCH  27
#define OMSZ  (B_*OMCH*HW_)   // 442368
#define NCHUNK 8

// GEMM chunking: k' = kk*256 + c; 72 chunks of 32 channels (kk 0..8, cgroup 0..7)
#define NCH   72
#define KPAD  40              // padded K row (elements) -> 80B rows, conflict-free ldmatrix

// Device scratch (no allocation allowed)
__device__ float  g_om[OMSZ];
__device__ float  g_om_part[NCHUNK * OMSZ];
// per chunk: [hi 256x40 bf16][lo 256x40 bf16] = 40960 B = 2560 float4
__device__ float4 g_wA[NCH * 2560];

// ---------------------------------------------------------------------------
// PTX helpers
// ---------------------------------------------------------------------------
__device__ __forceinline__ uint32_t s2u(const void* p) {
    uint32_t r;
    asm("{ .reg .u64 t; cvta.to.shared.u64 t, %1; cvt.u32.u64 %0, t; }" : "=r"(r) : "l"(p));
    return r;
}
__device__ __forceinline__ void ldsm4(uint32_t* r, uint32_t addr) {
    asm volatile("ldmatrix.sync.aligned.m8n8.x4.shared.b16 {%0,%1,%2,%3}, [%4];"
                 : "=r"(r[0]), "=r"(r[1]), "=r"(r[2]), "=r"(r[3]) : "r"(addr));
}
__device__ __forceinline__ void mma_bf16(float* d, const uint32_t* a, const uint32_t* b) {
    asm volatile(
        "mma.sync.aligned.m16n8k16.row.col.f32.bf16.bf16.f32 "
        "{%0,%1,%2,%3}, {%4,%5,%6,%7}, {%8,%9}, {%0,%1,%2,%3};"
        : "+f"(d[0]), "+f"(d[1]), "+f"(d[2]), "+f"(d[3])
        : "r"(a[0]), "r"(a[1]), "r"(a[2]), "r"(a[3]), "r"(b[0]), "r"(b[1]));
}

// ---------------------------------------------------------------------------
// Dynamic SMEM layout (byte offsets)
//   A: 2 bufs x (hi 20480 + lo 20480)      = 81920
//   B: 2 bufs x (hi 10240 + lo 10240)      = 40960
//   params: idxA/idxB 1152 u32 each, wq 1152 float4
// ---------------------------------------------------------------------------
#define SM_A     0
#define SM_B     81920
#define SM_IDXA  122880
#define SM_IDXB  127488
#define SM_WQ    132096
#define DYN_SMEM 150528

// ---------------------------------------------------------------------------
// Kernel 1: pack weights into bf16 hi/lo padded tiles
// ---------------------------------------------------------------------------
__global__ void prep_w_kernel(const float* __restrict__ weight) {
    int i = blockIdx.x * 256 + threadIdx.x;   // 0 .. 589823
    int chunk = i >> 13;            // /8192 (256 o * 32 kl)
    int rem   = i & 8191;
    int o     = rem >> 5;
    int kl    = rem & 31;
    int kk = chunk >> 3;
    int cg = chunk & 7;
    int c  = cg * 32 + kl;
    float w = weight[o * KTOT + c * 9 + kk];
    __nv_bfloat16 hi = __float2bfloat16(w);
    __nv_bfloat16 lo = __float2bfloat16(w - __bfloat162float(hi));
    __nv_bfloat16* base = (__nv_bfloat16*)g_wA + (size_t)chunk * 20480;
    base[o * KPAD + kl]         = hi;
    base[10240 + o * KPAD + kl] = lo;
}

// ---------------------------------------------------------------------------
// Kernel 2: offset conv partials (unchanged)
// ---------------------------------------------------------------------------
__global__ __launch_bounds__(128) void offset_conv_kernel(
    const float* __restrict__ x, const float* __restrict__ w_off)
{
    __shared__ float s_w[OMCH * 288];
    const int t     = threadIdx.x;
    const int c0    = blockIdx.y * 32;
    const int pbase = blockIdx.x * 512;
    const int b     = pbase >> 12;

    for (int i = t; i < OMCH * 288; i += 128) {
        int j = i / 288, col = i - j * 288;
        s_w[i] = w_off[j * KTOT + c0 * 9 + col];
    }
    __syncthreads();

    int pimg[4], hh[4], ww[4];
#pragma unroll
    for (int p = 0; p < 4; p++) {
        int pix = pbase + t + (p << 7);
        pimg[p] = pix & 4095;
        hh[p] = pimg[p] >> 6;
        ww[p] = pimg[p] & 63;
    }

    float acc[OMCH][4];
#pragma unroll
    for (int j = 0; j < OMCH; j++)
#pragma unroll
        for (int p = 0; p < 4; p++) acc[j][p] = 0.f;

    const float* xb = x + (((size_t)b * C_ + c0) << 12);
    for (int cl = 0; cl < 32; cl++) {
        const float* xc = xb + ((size_t)cl << 12);
#pragma unroll
        for (int kh = 0; kh < 3; kh++) {
#pragma unroll
            for (int kw = 0; kw < 3; kw++) {
                float xv[4];
#pragma unroll
                for (int p = 0; p < 4; p++) {
                    int y  = hh[p] + kh - 1;
                    int xx = ww[p] + kw - 1;
                    bool ok = ((unsigned)y < 64u) && ((unsigned)xx < 64u);
                    xv[p] = ok ? __ldg(xc + (y << 6) + xx) : 0.f;
                }
                int wbase = cl * 9 + kh * 3 + kw;
#pragma unroll
                for (int j = 0; j < OMCH; j++) {
                    float wv = s_w[j * 288 + wbase];
#pragma unroll
                    for (int p = 0; p < 4; p++) acc[j][p] = fmaf(wv, xv[p], acc[j][p]);
                }
            }
        }
    }

    float* dst = g_om_part + (size_t)blockIdx.y * OMSZ + (((size_t)b * OMCH) << 12);
#pragma unroll
    for (int j = 0; j < OMCH; j++)
#pragma unroll
        for (int p = 0; p < 4; p++)
            dst[(j << 12) + pimg[p]] = acc[j][p];
}

__global__ void reduce_om_kernel(const float* __restrict__ b_off) {
    int i = blockIdx.x * 256 + threadIdx.x;
    float s = b_off[(i >> 12) % OMCH];
#pragma unroll
    for (int k = 0; k < NCHUNK; k++) s += g_om_part[(size_t)k * OMSZ + i];
    g_om[i] = s;
}

// ---------------------------------------------------------------------------
// Kernel 3: fused bilinear-sample + bf16 3-pass mma.sync GEMM.
// grid = 128 CTAs (128-pixel tiles), 512 threads = 16 warps (4 M-groups x 4 N).
// ---------------------------------------------------------------------------
__global__ __launch_bounds__(512, 1) void dcn_mma_kernel(
    const float* __restrict__ x, const float* __restrict__ bias,
    float* __restrict__ out)
{
    extern __shared__ char smem[];
    uint32_t sb = s2u(smem);

    const int t    = threadIdx.x;
    const int lane = t & 31;
    const int wid  = t >> 5;
    const int mw   = wid >> 2;     // 0..3 -> rows mw*64..
    const int nw   = wid & 3;      // 0..3 -> cols nw*32..
    const int pbase = blockIdx.x * 128;
    const int b     = pbase >> 12;
    const int pib   = pbase & 4095;

    uint32_t* s_idxA = (uint32_t*)(smem + SM_IDXA);
    uint32_t* s_idxB = (uint32_t*)(smem + SM_IDXB);
    float4*   s_wq   = (float4*)(smem + SM_WQ);

    // ---- sampling params: 9 kk x 128 pixels ----
    for (int e = t; e < KK_ * 128; e += 512) {
        int kk = e >> 7;
        int n  = e & 127;
        int pimg = pib + n;
        int h = pimg >> 6, w = pimg & 63;
        const float* omb = g_om + (((size_t)b * OMCH) << 12) + pimg;
        float dy = omb[(size_t)(2 * kk) << 12];
        float dx = omb[(size_t)(2 * kk + 1) << 12];
        float mv = omb[(size_t)(18 + kk) << 12];
        float m  = 1.0f / (1.0f + expf(-mv));
        int kh = kk / 3, kw = kk - 3 * kh;
        float py = (float)(h - 1 + kh) + dy;
        float px = (float)(w - 1 + kw) + dx;
        float y0f = floorf(py), x0f = floorf(px);
        float ly = py - y0f, lx = px - x0f;
        int y0 = (int)y0f, x0 = (int)x0f;
        int y1 = y0 + 1, x1 = x0 + 1;
        float vy0 = ((unsigned)y0 < 64u) ? 1.f : 0.f;
        float vy1 = ((unsigned)y1 < 64u) ? 1.f : 0.f;
        float vx0 = ((unsigned)x0 < 64u) ? 1.f : 0.f;
        float vx1 = ((unsigned)x1 < 64u) ? 1.f : 0.f;
        int y0c = min(max(y0, 0), 63), y1c = min(max(y1, 0), 63);
        int x0c = min(max(x0, 0), 63), x1c = min(max(x1, 0), 63);
        float w00 = (1.f - ly) * (1.f - lx) * m * vy0 * vx0;
        float w01 = (1.f - ly) * lx * m * vy0 * vx1;
        float w10 = ly * (1.f - lx) * m * vy1 * vx0;
        float w11 = ly * lx * m * vy1 * vx1;
        s_idxA[e] = (uint32_t)(y0c * 64 + x0c) | ((uint32_t)(y0c * 64 + x1c) << 16);
        s_idxB[e] = (uint32_t)(y1c * 64 + x0c) | ((uint32_t)(y1c * 64 + x1c) << 16);
        s_wq[e] = make_float4(w00, w01, w10, w11);
    }
    __syncthreads();

    float acc[4][4][4];
#pragma unroll
    for (int i = 0; i < 4; i++)
#pragma unroll
        for (int j = 0; j < 4; j++)
#pragma unroll
            for (int q = 0; q < 4; q++) acc[i][j][q] = 0.f;

    // per-thread ldmatrix base offsets (bytes within a tile)
    const uint32_t a_off = (uint32_t)((lane & 15) * 80 + ((lane >> 4) << 4));
    const uint32_t b_off = (uint32_t)((((lane >> 4) << 3) + (lane & 7)) * 80
                                      + (((lane >> 3) & 1) << 4));

    const float* xb = x + ((size_t)b << 20);
    const int nloc  = t & 127;     // pixel-in-tile this thread produces
    const int klq   = t >> 7;      // 0..3: channel sub-slot

    for (int c = 0; c < NCH; c++) {
        const int buf = c & 1;

        // ---- produce A (plain coalesced copy of prepacked tiles) ----
        {
            const float4* srcA = g_wA + (size_t)c * 2560;
            float4* dA = (float4*)(smem + SM_A + buf * 40960);
#pragma unroll
            for (int r = 0; r < 5; r++) dA[t + (r << 9)] = srcA[t + (r << 9)];
        }

        // ---- produce B: bilinear gathers for 32 channels x 128 pixels ----
        {
            const int kk = c >> 3;
            const int cg = c & 7;
            const int e  = (kk << 7) + nloc;
            const uint32_t ia = s_idxA[e], ib2 = s_idxB[e];
            const float4 wq = s_wq[e];
            const int i00 = ia & 0xffff,  i01 = ia >> 16;
            const int i10 = ib2 & 0xffff, i11 = ib2 >> 16;
            const float* xch = xb + ((size_t)(cg * 32 + klq) << 12);
            __nv_bfloat16* bh = (__nv_bfloat16*)(smem + SM_B + buf * 20480);
            __nv_bfloat16* bl = bh + 5120;
#pragma unroll
            for (int j = 0; j < 8; j++) {
                const float* xc = xch + ((size_t)j << 14);   // +4 channels
                float v = wq.x * __ldg(xc + i00) + wq.y * __ldg(xc + i01)
                        + wq.z * __ldg(xc + i10) + wq.w * __ldg(xc + i11);
                __nv_bfloat16 hi = __float2bfloat16(v);
                __nv_bfloat16 lo = __float2bfloat16(v - __bfloat162float(hi));
                int kl = klq + (j << 2);
                bh[nloc * KPAD + kl] = hi;
                bl[nloc * KPAD + kl] = lo;
            }
        }
        __syncthreads();

        // ---- consume: 3 passes (AhBh, AhBl, AlBh), K=32 per chunk ----
#pragma unroll
        for (int pass = 0; pass < 3; pass++) {
            uint32_t Ab = sb + SM_A + buf * 40960 + (pass == 2 ? 20480 : 0);
            uint32_t Bb = sb + SM_B + buf * 20480 + (pass == 1 ? 10240 : 0);
#pragma unroll
            for (int h = 0; h < 2; h++) {
                uint32_t af[4][4], bfr[2][4];
#pragma unroll
                for (int mi = 0; mi < 4; mi++)
                    ldsm4(af[mi], Ab + a_off + (uint32_t)((mw * 64 + mi * 16) * 80 + h * 32));
#pragma unroll
                for (int p = 0; p < 2; p++)
                    ldsm4(bfr[p], Bb + b_off + (uint32_t)((nw * 32 + p * 16) * 80 + h * 32));
#pragma unroll
                for (int mi = 0; mi < 4; mi++)
#pragma unroll
                    for (int p = 0; p < 2; p++) {
                        mma_bf16(acc[mi][2 * p],     af[mi], &bfr[p][0]);
                        mma_bf16(acc[mi][2 * p + 1], af[mi], &bfr[p][2]);
                    }
            }
        }
    }

    // ---- epilogue: bias + store ----
    const int m0   = mw * 64 + (lane >> 2);
    const int col0 = nw * 32 + ((lane & 3) << 1);
#pragma unroll
    for (int mi = 0; mi < 4; mi++) {
        int o = m0 + mi * 16;
        float bv0 = __ldg(bias + o);
        float bv1 = __ldg(bias + o + 8);
        float* r0 = out + (((size_t)(b * O_ + o)) << 12) + pib;
        float* r1 = r0 + (8 << 12);
#pragma unroll
        for (int nj = 0; nj < 4; nj++) {
            int cc = col0 + nj * 8;
            float2 v0 = make_float2(acc[mi][nj][0] + bv0, acc[mi][nj][1] + bv0);
            float2 v1 = make_float2(acc[mi][nj][2] + bv1, acc[mi][nj][3] + bv1);
            *(float2*)(r0 + cc) = v0;
            *(float2*)(r1 + cc) = v1;
        }
    }
}

// ---------------------------------------------------------------------------
// Launch
// ---------------------------------------------------------------------------
extern "C" void kernel_launch(void* const* d_in, const int* in_sizes, int n_in,
                              void* d_out, int out_size)
{
    const float* x      = (const float*)d_in[0];
    const float* w_off  = (const float*)d_in[1];
    const float* b_off  = (const float*)d_in[2];
    const float* weight = (const float*)d_in[3];
    const float* bias   = (const float*)d_in[4];
    float* out = (float*)d_out;

    static int configured = 0;
    cudaFuncSetAttribute(dcn_mma_kernel,
                         cudaFuncAttributeMaxDynamicSharedMemorySize, DYN_SMEM);
    (void)configured;

    // 1) weight pack (589824 elements)
    prep_w_kernel<<<2304, 256>>>(weight);

    // 2) offset conv partials + reduce
    offset_conv_kernel<<<dim3(32, NCHUNK), 128>>>(x, w_off);
    reduce_om_kernel<<<OMSZ / 256, 256>>>(b_off);

    // 3) fused sample + mma GEMM
    dcn_mma_kernel<<<NPIX / 128, 512, DYN_SMEM>>>(x, bias, out);
}

// round 4
// speedup vs baseline: 2.9124x; 1.1673x over previous
#include <cuda_runtime.h>
#include <cuda_bf16.h>
#include <cstdint>

// Problem constants
#define B_    4
#define C_    256
#define H_    64
#define W_    64
#define O_    256
#define KK_   9
#define HW_   4096
#define NPIX  16384
#define KTOT  2304
#define OMCH  27
#define OMSZ  (B_*OMCH*HW_)   // 442368
#define NCHUNK 8

// GEMM chunking: k' = kk*256 + c; 72 chunks of 32 channels
#define NCH   72
#define KPAD  40              // padded K row -> 80B rows, conflict-free ldmatrix/STS.128

// Device scratch
__device__ float  g_om[OMSZ];
__device__ float  g_om_part[NCHUNK * OMSZ];
// per chunk: [hi 256x40 bf16][lo 256x40 bf16] = 40960 B = 2560 float4
__device__ float4 g_wA[NCH * 2560];

// ---------------------------------------------------------------------------
// PTX helpers
// ---------------------------------------------------------------------------
__device__ __forceinline__ uint32_t s2u(const void* p) {
    uint32_t r;
    asm("{ .reg .u64 t; cvta.to.shared.u64 t, %1; cvt.u32.u64 %0, t; }" : "=r"(r) : "l"(p));
    return r;
}
__device__ __forceinline__ void ldsm4(uint32_t* r, uint32_t addr) {
    asm volatile("ldmatrix.sync.aligned.m8n8.x4.shared.b16 {%0,%1,%2,%3}, [%4];"
                 : "=r"(r[0]), "=r"(r[1]), "=r"(r[2]), "=r"(r[3]) : "r"(addr));
}
__device__ __forceinline__ void mma_bf16(float* d, const uint32_t* a, const uint32_t* b) {
    asm volatile(
        "mma.sync.aligned.m16n8k16.row.col.f32.bf16.bf16.f32 "
        "{%0,%1,%2,%3}, {%4,%5,%6,%7}, {%8,%9}, {%0,%1,%2,%3};"
        : "+f"(d[0]), "+f"(d[1]), "+f"(d[2]), "+f"(d[3])
        : "r"(a[0]), "r"(a[1]), "r"(a[2]), "r"(a[3]), "r"(b[0]), "r"(b[1]));
}
__device__ __forceinline__ void cp_async16(uint32_t dst, const void* src) {
    asm volatile("cp.async.cg.shared.global [%0], [%1], 16;" :: "r"(dst), "l"(src));
}
__device__ __forceinline__ void cp_commit() {
    asm volatile("cp.async.commit_group;" ::: "memory");
}
__device__ __forceinline__ void cp_wait0() {
    asm volatile("cp.async.wait_group 0;" ::: "memory");
}

// ---------------------------------------------------------------------------
// SMEM layout
//   A: 2 bufs x (hi 20480 + lo 20480)      = 81920
//   B: 2 bufs x (hi 10240 + lo 10240)      = 40960
//   params: idxA/idxB 1152 u32 each, wq 1152 float4
// ---------------------------------------------------------------------------
#define SM_A     0
#define SM_B     81920
#define SM_IDXA  122880
#define SM_IDXB  127488
#define SM_WQ    132096
#define DYN_SMEM 150528

// ---------------------------------------------------------------------------
// Kernel 1: pack weights into bf16 hi/lo padded tiles
// ---------------------------------------------------------------------------
__global__ void prep_w_kernel(const float* __restrict__ weight) {
    int i = blockIdx.x * 256 + threadIdx.x;   // 0 .. 589823
    int chunk = i >> 13;
    int rem   = i & 8191;
    int o     = rem >> 5;
    int kl    = rem & 31;
    int kk = chunk >> 3;
    int cg = chunk & 7;
    int c  = cg * 32 + kl;
    float w = weight[o * KTOT + c * 9 + kk];
    __nv_bfloat16 hi = __float2bfloat16(w);
    __nv_bfloat16 lo = __float2bfloat16(w - __bfloat162float(hi));
    __nv_bfloat16* base = (__nv_bfloat16*)g_wA + (size_t)chunk * 20480;
    base[o * KPAD + kl]         = hi;
    base[10240 + o * KPAD + kl] = lo;
}

// ---------------------------------------------------------------------------
// Kernel 2: offset conv partials (unchanged)
// ---------------------------------------------------------------------------
__global__ __launch_bounds__(128) void offset_conv_kernel(
    const float* __restrict__ x, const float* __restrict__ w_off)
{
    __shared__ float s_w[OMCH * 288];
    const int t     = threadIdx.x;
    const int c0    = blockIdx.y * 32;
    const int pbase = blockIdx.x * 512;
    const int b     = pbase >> 12;

    for (int i = t; i < OMCH * 288; i += 128) {
        int j = i / 288, col = i - j * 288;
        s_w[i] = w_off[j * KTOT + c0 * 9 + col];
    }
    __syncthreads();

    int pimg[4], hh[4], ww[4];
#pragma unroll
    for (int p = 0; p < 4; p++) {
        int pix = pbase + t + (p << 7);
        pimg[p] = pix & 4095;
        hh[p] = pimg[p] >> 6;
        ww[p] = pimg[p] & 63;
    }

    float acc[OMCH][4];
#pragma unroll
    for (int j = 0; j < OMCH; j++)
#pragma unroll
        for (int p = 0; p < 4; p++) acc[j][p] = 0.f;

    const float* xb = x + (((size_t)b * C_ + c0) << 12);
    for (int cl = 0; cl < 32; cl++) {
        const float* xc = xb + ((size_t)cl << 12);
#pragma unroll
        for (int kh = 0; kh < 3; kh++) {
#pragma unroll
            for (int kw = 0; kw < 3; kw++) {
                float xv[4];
#pragma unroll
                for (int p = 0; p < 4; p++) {
                    int y  = hh[p] + kh - 1;
                    int xx = ww[p] + kw - 1;
                    bool ok = ((unsigned)y < 64u) && ((unsigned)xx < 64u);
                    xv[p] = ok ? __ldg(xc + (y << 6) + xx) : 0.f;
                }
                int wbase = cl * 9 + kh * 3 + kw;
#pragma unroll
                for (int j = 0; j < OMCH; j++) {
                    float wv = s_w[j * 288 + wbase];
#pragma unroll
                    for (int p = 0; p < 4; p++) acc[j][p] = fmaf(wv, xv[p], acc[j][p]);
                }
            }
        }
    }

    float* dst = g_om_part + (size_t)blockIdx.y * OMSZ + (((size_t)b * OMCH) << 12);
#pragma unroll
    for (int j = 0; j < OMCH; j++)
#pragma unroll
        for (int p = 0; p < 4; p++)
            dst[(j << 12) + pimg[p]] = acc[j][p];
}

__global__ void reduce_om_kernel(const float* __restrict__ b_off) {
    int i = blockIdx.x * 256 + threadIdx.x;
    float s = b_off[(i >> 12) % OMCH];
#pragma unroll
    for (int k = 0; k < NCHUNK; k++) s += g_om_part[(size_t)k * OMSZ + i];
    g_om[i] = s;
}

// ---------------------------------------------------------------------------
// Kernel 3: fused bilinear-sample + bf16 3-pass mma.sync GEMM, pipelined.
// grid = 128 CTAs (128-pixel tiles), 512 threads = 16 warps (4 M x 4 N).
// Chunk c+1 gathers (registers) + A tile (cp.async) overlap chunk c MMAs.
// ---------------------------------------------------------------------------
struct GatherCtx {
    int i00, i01, i10, i11;
    float4 wq;
    const float* xch;   // channel base for this thread (klq*8)
};

__device__ __forceinline__ void gather_issue(const GatherCtx& g, int grp, float* r) {
    const float* xc0 = g.xch + ((size_t)(2 * grp) << 12);
    const float* xc1 = xc0 + 4096;
    r[0] = __ldg(xc0 + g.i00); r[1] = __ldg(xc0 + g.i01);
    r[2] = __ldg(xc0 + g.i10); r[3] = __ldg(xc0 + g.i11);
    r[4] = __ldg(xc1 + g.i00); r[5] = __ldg(xc1 + g.i01);
    r[6] = __ldg(xc1 + g.i10); r[7] = __ldg(xc1 + g.i11);
}
__device__ __forceinline__ void gather_combine(const GatherCtx& g, const float* r,
                                               float& v0, float& v1) {
    v0 = g.wq.x * r[0] + g.wq.y * r[1] + g.wq.z * r[2] + g.wq.w * r[3];
    v1 = g.wq.x * r[4] + g.wq.y * r[5] + g.wq.z * r[6] + g.wq.w * r[7];
}

__device__ __forceinline__ void mma_subpass(uint32_t Ab, uint32_t Bb,
                                            uint32_t a_off, uint32_t b_off,
                                            int mw, int nw, int h,
                                            float (*acc)[4][4]) {
    uint32_t af[4][4], bfr[2][4];
#pragma unroll
    for (int mi = 0; mi < 4; mi++)
        ldsm4(af[mi], Ab + a_off + (uint32_t)((mw * 64 + mi * 16) * 80 + h * 32));
#pragma unroll
    for (int p = 0; p < 2; p++)
        ldsm4(bfr[p], Bb + b_off + (uint32_t)((nw * 32 + p * 16) * 80 + h * 32));
#pragma unroll
    for (int mi = 0; mi < 4; mi++)
#pragma unroll
        for (int p = 0; p < 2; p++) {
            mma_bf16(acc[mi][2 * p],     af[mi], &bfr[p][0]);
            mma_bf16(acc[mi][2 * p + 1], af[mi], &bfr[p][2]);
        }
}

__global__ __launch_bounds__(512, 1) void dcn_mma_kernel(
    const float* __restrict__ x, const float* __restrict__ bias,
    float* __restrict__ out)
{
    extern __shared__ char smem[];
    uint32_t sb = s2u(smem);

    const int t    = threadIdx.x;
    const int lane = t & 31;
    const int wid  = t >> 5;
    const int mw   = wid >> 2;
    const int nw   = wid & 3;
    const int pbase = blockIdx.x * 128;
    const int b     = pbase >> 12;
    const int pib   = pbase & 4095;

    uint32_t* s_idxA = (uint32_t*)(smem + SM_IDXA);
    uint32_t* s_idxB = (uint32_t*)(smem + SM_IDXB);
    float4*   s_wq   = (float4*)(smem + SM_WQ);

    // ---- sampling params: 9 kk x 128 pixels ----
    for (int e = t; e < KK_ * 128; e += 512) {
        int kk = e >> 7;
        int n  = e & 127;
        int pimg = pib + n;
        int h = pimg >> 6, w = pimg & 63;
        const float* omb = g_om + (((size_t)b * OMCH) << 12) + pimg;
        float dy = omb[(size_t)(2 * kk) << 12];
        float dx = omb[(size_t)(2 * kk + 1) << 12];
        float mv = omb[(size_t)(18 + kk) << 12];
        float m  = 1.0f / (1.0f + expf(-mv));
        int kh = kk / 3, kw = kk - 3 * kh;
        float py = (float)(h - 1 + kh) + dy;
        float px = (float)(w - 1 + kw) + dx;
        float y0f = floorf(py), x0f = floorf(px);
        float ly = py - y0f, lx = px - x0f;
        int y0 = (int)y0f, x0 = (int)x0f;
        int y1 = y0 + 1, x1 = x0 + 1;
        float vy0 = ((unsigned)y0 < 64u) ? 1.f : 0.f;
        float vy1 = ((unsigned)y1 < 64u) ? 1.f : 0.f;
        float vx0 = ((unsigned)x0 < 64u) ? 1.f : 0.f;
        float vx1 = ((unsigned)x1 < 64u) ? 1.f : 0.f;
        int y0c = min(max(y0, 0), 63), y1c = min(max(y1, 0), 63);
        int x0c = min(max(x0, 0), 63), x1c = min(max(x1, 0), 63);
        float w00 = (1.f - ly) * (1.f - lx) * m * vy0 * vx0;
        float w01 = (1.f - ly) * lx * m * vy0 * vx1;
        float w10 = ly * (1.f - lx) * m * vy1 * vx0;
        float w11 = ly * lx * m * vy1 * vx1;
        s_idxA[e] = (uint32_t)(y0c * 64 + x0c) | ((uint32_t)(y0c * 64 + x1c) << 16);
        s_idxB[e] = (uint32_t)(y1c * 64 + x0c) | ((uint32_t)(y1c * 64 + x1c) << 16);
        s_wq[e] = make_float4(w00, w01, w10, w11);
    }
    __syncthreads();

    float acc[4][4][4];
#pragma unroll
    for (int i = 0; i < 4; i++)
#pragma unroll
        for (int j = 0; j < 4; j++)
#pragma unroll
            for (int q = 0; q < 4; q++) acc[i][j][q] = 0.f;

    const uint32_t a_off = (uint32_t)((lane & 15) * 80 + ((lane >> 4) << 4));
    const uint32_t b_off = (uint32_t)((((lane >> 4) << 3) + (lane & 7)) * 80
                                      + (((lane >> 3) & 1) << 4));

    const float* xb = x + ((size_t)b << 20);
    const int nloc  = t & 127;     // pixel this thread produces
    const int klq   = t >> 7;      // channel octet: kl = klq*8 + j

    // load gather context for a chunk
    auto load_ctx = [&](int c, GatherCtx& g) {
        int kk = c >> 3, cg = c & 7;
        int e  = (kk << 7) + nloc;
        uint32_t ia = s_idxA[e], ib2 = s_idxB[e];
        g.i00 = ia & 0xffff;  g.i01 = ia >> 16;
        g.i10 = ib2 & 0xffff; g.i11 = ib2 >> 16;
        g.wq  = s_wq[e];
        g.xch = xb + ((size_t)(cg * 32 + klq * 8) << 12);
    };

    uint32_t ph[4], pl[4];   // packed B rows for the chunk about to be stored

    // ---- prologue: A(0) via cp.async, B(0) gathered into registers ----
    {
        const float4* srcA = g_wA;
        uint32_t dA = sb + SM_A;
#pragma unroll
        for (int r = 0; r < 5; r++)
            cp_async16(dA + (uint32_t)((t + (r << 9)) << 4), srcA + t + (r << 9));
        cp_commit();

        GatherCtx g; load_ctx(0, g);
        float v[8], r[8];
#pragma unroll
        for (int grp = 0; grp < 4; grp++) {
            gather_issue(g, grp, r);
            gather_combine(g, r, v[2 * grp], v[2 * grp + 1]);
        }
#pragma unroll
        for (int q = 0; q < 4; q++) {
            uint32_t ua = __float_as_uint(v[2 * q]);
            uint32_t ub = __float_as_uint(v[2 * q + 1]);
            float ta = __uint_as_float(ua & 0xffff0000u);
            float tb = __uint_as_float(ub & 0xffff0000u);
            ph[q] = __byte_perm(ua, ub, 0x7632);
            pl[q] = __byte_perm(__float_as_uint(v[2 * q] - ta),
                                __float_as_uint(v[2 * q + 1] - tb), 0x7632);
        }
    }

    const uint32_t bstore = (uint32_t)(nloc * 80 + klq * 16);

    for (int c = 0; c < NCH; c++) {
        const int buf = c & 1;

        // ---- STS B(c) : 2x STS.128, conflict-free ----
        {
            char* bh = smem + SM_B + buf * 20480 + bstore;
            *(float4*)bh             = *(float4*)ph;
            *(float4*)(bh + 10240)   = *(float4*)pl;
        }
        cp_wait0();          // A(c) resident
        __syncthreads();     // buffers for chunk c visible to all

        const bool pf = (c + 1 < NCH);

        // ---- issue A(c+1) ----
        if (pf) {
            const float4* srcA = g_wA + (size_t)(c + 1) * 2560;
            uint32_t dA = sb + SM_A + (buf ^ 1) * 40960;
#pragma unroll
            for (int r = 0; r < 5; r++)
                cp_async16(dA + (uint32_t)((t + (r << 9)) << 4), srcA + t + (r << 9));
            cp_commit();
        }

        GatherCtx g;
        if (pf) load_ctx(c + 1, g);

        const uint32_t A0 = sb + SM_A + buf * 40960;
        const uint32_t B0 = sb + SM_B + buf * 20480;

        float v[8], r[8];
        // interleave: gather group i issued before subpass i, combined after it
        if (pf) gather_issue(g, 0, r);
        mma_subpass(A0,         B0,         a_off, b_off, mw, nw, 0, acc);
        if (pf) { gather_combine(g, r, v[0], v[1]); gather_issue(g, 1, r); }
        mma_subpass(A0,         B0,         a_off, b_off, mw, nw, 1, acc);
        if (pf) { gather_combine(g, r, v[2], v[3]); gather_issue(g, 2, r); }
        mma_subpass(A0,         B0 + 10240, a_off, b_off, mw, nw, 0, acc);
        if (pf) { gather_combine(g, r, v[4], v[5]); gather_issue(g, 3, r); }
        mma_subpass(A0,         B0 + 10240, a_off, b_off, mw, nw, 1, acc);
        if (pf) {
            gather_combine(g, r, v[6], v[7]);
#pragma unroll
            for (int q = 0; q < 4; q++) {
                uint32_t ua = __float_as_uint(v[2 * q]);
                uint32_t ub = __float_as_uint(v[2 * q + 1]);
                float ta = __uint_as_float(ua & 0xffff0000u);
                float tb = __uint_as_float(ub & 0xffff0000u);
                ph[q] = __byte_perm(ua, ub, 0x7632);
                pl[q] = __byte_perm(__float_as_uint(v[2 * q] - ta),
                                    __float_as_uint(v[2 * q + 1] - tb), 0x7632);
            }
        }
        mma_subpass(A0 + 20480, B0,         a_off, b_off, mw, nw, 0, acc);
        mma_subpass(A0 + 20480, B0,         a_off, b_off, mw, nw, 1, acc);
    }

    // ---- epilogue: bias + store ----
    const int m0   = mw * 64 + (lane >> 2);
    const int col0 = nw * 32 + ((lane & 3) << 1);
#pragma unroll
    for (int mi = 0; mi < 4; mi++) {
        int o = m0 + mi * 16;
        float bv0 = __ldg(bias + o);
        float bv1 = __ldg(bias + o + 8);
        float* r0 = out + (((size_t)(b * O_ + o)) << 12) + pib;
        float* r1 = r0 + (8 << 12);
#pragma unroll
        for (int nj = 0; nj < 4; nj++) {
            int cc = col0 + nj * 8;
            float2 v0 = make_float2(acc[mi][nj][0] + bv0, acc[mi][nj][1] + bv0);
            float2 v1 = make_float2(acc[mi][nj][2] + bv1, acc[mi][nj][3] + bv1);
            *(float2*)(r0 + cc) = v0;
            *(float2*)(r1 + cc) = v1;
        }
    }
}

// ---------------------------------------------------------------------------
// Launch
// ---------------------------------------------------------------------------
extern "C" void kernel_launch(void* const* d_in, const int* in_sizes, int n_in,
                              void* d_out, int out_size)
{
    const float* x      = (const float*)d_in[0];
    const float* w_off  = (const float*)d_in[1];
    const float* b_off  = (const float*)d_in[2];
    const float* weight = (const float*)d_in[3];
    const float* bias   = (const float*)d_in[4];
    float* out = (float*)d_out;

    cudaFuncSetAttribute(dcn_mma_kernel,
                         cudaFuncAttributeMaxDynamicSharedMemorySize, DYN_SMEM);

    prep_w_kernel<<<2304, 256>>>(weight);
    offset_conv_kernel<<<dim3(32, NCHUNK), 128>>>(x, w_off);
    reduce_om_kernel<<<OMSZ / 256, 256>>>(b_off);
    dcn_mma_kernel<<<NPIX / 128, 512, DYN_SMEM>>>(x, bias, out);
}